// round 12
// baseline (speedup 1.0000x reference)
#include <cuda_runtime.h>
#include <cuda_bf16.h>
#include <math.h>

#define NVARS 8
#define NBINS 128

// Scratch: per-column min/max in order-preserving uint encoding.
__device__ unsigned g_min_u[NVARS];
__device__ unsigned g_max_u[NVARS];

__device__ __forceinline__ unsigned f2o(float f) {
    unsigned u = __float_as_uint(f);
    return u ^ ((unsigned)((int)u >> 31) | 0x80000000u);
}
__device__ __forceinline__ float o2f(unsigned u) {
    unsigned b = (u & 0x80000000u) ? (u ^ 0x80000000u) : ~u;
    return __uint_as_float(b);
}

__global__ void init_minmax_kernel() {
    int i = threadIdx.x;
    if (i < NVARS) {
        g_min_u[i] = 0xFFFFFFFFu;
        g_max_u[i] = 0x00000000u;
    }
}

__global__ void minmax_kernel(const float* __restrict__ feats, int nrows) {
    int tid = blockIdx.x * blockDim.x + threadIdx.x;
    int stride = gridDim.x * blockDim.x;

    float mn[NVARS], mx[NVARS];
#pragma unroll
    for (int c = 0; c < NVARS; c++) { mn[c] = INFINITY; mx[c] = -INFINITY; }

    for (int r = tid; r < nrows; r += stride) {
        const float4* p = reinterpret_cast<const float4*>(feats + (size_t)r * NVARS);
        float4 a = p[0];
        float4 b = p[1];
        mn[0] = fminf(mn[0], a.x); mx[0] = fmaxf(mx[0], a.x);
        mn[1] = fminf(mn[1], a.y); mx[1] = fmaxf(mx[1], a.y);
        mn[2] = fminf(mn[2], a.z); mx[2] = fmaxf(mx[2], a.z);
        mn[3] = fminf(mn[3], a.w); mx[3] = fmaxf(mx[3], a.w);
        mn[4] = fminf(mn[4], b.x); mx[4] = fmaxf(mx[4], b.x);
        mn[5] = fminf(mn[5], b.y); mx[5] = fmaxf(mx[5], b.y);
        mn[6] = fminf(mn[6], b.z); mx[6] = fmaxf(mx[6], b.z);
        mn[7] = fminf(mn[7], b.w); mx[7] = fmaxf(mx[7], b.w);
    }

#pragma unroll
    for (int off = 16; off > 0; off >>= 1) {
#pragma unroll
        for (int c = 0; c < NVARS; c++) {
            mn[c] = fminf(mn[c], __shfl_xor_sync(0xFFFFFFFFu, mn[c], off));
            mx[c] = fmaxf(mx[c], __shfl_xor_sync(0xFFFFFFFFu, mx[c], off));
        }
    }

    if ((threadIdx.x & 31) == 0) {
#pragma unroll
        for (int c = 0; c < NVARS; c++) {
            atomicMin(&g_min_u[c], f2o(mn[c]));
            atomicMax(&g_max_u[c], f2o(mx[c]));
        }
    }
}

// t_b = b / 127 computed with PTX div.full.f32 — the fast full-range division
// Triton emits for f32 '/', used by XLA's Triton reduction emitter when it
// re-materializes the iota in-kernel. Differs from div.rn by <=1 ulp at a
// sparse subset of b.
__device__ __forceinline__ float t_divfull(int b) {
    float t;
    float fb = (float)b;
    asm("div.full.f32 %0, %1, %2;" : "=f"(t) : "f"(fb), "f"(127.0f));
    return t;
}

// Criterion rollout: L1 tree (plain rn mul/add/sub/mul), t via div.full.
__device__ __forceinline__ bool diff_nonpos(float fminv, float d, float feat, int b) {
    float t   = t_divfull(b);
    float dt  = __fmul_rn(d, t);
    float lin = __fadd_rn(fminv, dt);
    float y   = __fmul_rn(__fsub_rn(lin, feat), 1000000.0f);
    return rintf(y) <= 0.0f;
}

// vals/step rollout: materialized lin = fmin + d * rn(b/127), plain mul+add.
__device__ __forceinline__ float lin_at(float fminv, float d, int b) {
    float t = __fdiv_rn((float)b, 127.0f);
    return __fadd_rn(fminv, __fmul_rn(d, t));
}

__global__ void quantize_kernel(const float* __restrict__ feats,
                                float* __restrict__ out_bins,
                                float* __restrict__ out_regs,
                                int n) {
    int idx = blockIdx.x * blockDim.x + threadIdx.x;
    if (idx >= n) return;

    int c = idx & (NVARS - 1);
    float fminv = o2f(g_min_u[c]);
    float fmaxv = o2f(g_max_u[c]);
    float d = __fsub_rn(fmaxv, fminv);

    // step = lin[1] - lin[0]; lin[0] == fmin exactly
    float step = __fsub_rn(lin_at(fminv, d, 1), fminv);

    float feat = feats[idx];

    // Initial guess, then exact fixup under the (monotone) criterion.
    float g = (d > 0.0f) ? ((feat - fminv) / d) * 127.0f : 0.0f;
    int b = (int)g;
    b = max(0, min(NBINS - 1, b));

    while (b < NBINS - 1 && diff_nonpos(fminv, d, feat, b + 1)) b++;
    while (b > 0 && !diff_nonpos(fminv, d, feat, b)) b--;

    float val = lin_at(fminv, d, b);
    float r   = __fdiv_rn(fmaxf(__fsub_rn(feat, val), 0.0f), step);

    out_bins[idx] = (float)b;
    out_regs[idx] = r;
}

extern "C" void kernel_launch(void* const* d_in, const int* in_sizes, int n_in,
                              void* d_out, int out_size) {
    const float* feats = (const float*)d_in[0];
    int n = in_sizes[0];
    int nrows = n / NVARS;

    float* out = (float*)d_out;
    float* out_bins = out;
    float* out_regs = out + n;

    init_minmax_kernel<<<1, 32>>>();

    int rb = 96, rt = 256;
    minmax_kernel<<<rb, rt>>>(feats, nrows);

    int qt = 256;
    int qb = (n + qt - 1) / qt;
    quantize_kernel<<<qb, qt>>>(feats, out_bins, out_regs, n);
}